// round 14
// baseline (speedup 1.0000x reference)
#include <cuda_runtime.h>
#include <cuda_fp16.h>
#include <cstdint>

#define EPS 1e-6f

// ---------------- scratch (__device__ globals; no allocations allowed) -----
__device__ __half g_q16[16777216];   // att+conv result fp16 (A of GEMM2)
__device__ __half g_k16[16777216];
__device__ __half g_v16[16777216];
__device__ float g_kmean[4096];      // (B,1024)
__device__ __half g_kvt16[262144];   // kv^T fp16: [b,h][e][d]
__device__ float g_kvp[2097152];     // kv partials: [8 nc][B][h][64][64]
__device__ float g_kmp[32768];       // kmean partials: [8 nc][B][1024]
__device__ __half g_a16[16777216];   // x fp16
__device__ __half g_w16[4194304];    // transposed weights fp16 [WqT|WkvT|WprojT]
__device__ int g_cnt[64];            // kvmat finisher counters

// ---------------- PTX helpers (baseline sm_80+ features only) --------------
__device__ __forceinline__ uint32_t smem_u32(const void* p) {
    uint32_t a;
    asm("{ .reg .u64 t; cvta.to.shared.u64 t, %1; cvt.u32.u64 %0, t; }"
        : "=r"(a) : "l"(p));
    return a;
}
__device__ __forceinline__ void cpa16(uint32_t s, const void* g) {
    asm volatile("cp.async.cg.shared.global [%0], [%1], 16;" :: "r"(s), "l"(g));
}
__device__ __forceinline__ void ldmx4(uint32_t* r, uint32_t a) {
    asm volatile("ldmatrix.sync.aligned.m8n8.x4.shared.b16 {%0,%1,%2,%3}, [%4];"
                 : "=r"(r[0]), "=r"(r[1]), "=r"(r[2]), "=r"(r[3]) : "r"(a));
}
__device__ __forceinline__ void ldmx4t(uint32_t* r, uint32_t a) {
    asm volatile("ldmatrix.sync.aligned.m8n8.x4.trans.shared.b16 {%0,%1,%2,%3}, [%4];"
                 : "=r"(r[0]), "=r"(r[1]), "=r"(r[2]), "=r"(r[3]) : "r"(a));
}
__device__ __forceinline__ void mma16816(float* c, const uint32_t* a,
                                         uint32_t b0, uint32_t b1) {
    asm volatile(
        "mma.sync.aligned.m16n8k16.row.col.f32.f16.f16.f32 "
        "{%0,%1,%2,%3},{%4,%5,%6,%7},{%8,%9},{%0,%1,%2,%3};"
        : "+f"(c[0]), "+f"(c[1]), "+f"(c[2]), "+f"(c[3])
        : "r"(a[0]), "r"(a[1]), "r"(a[2]), "r"(a[3]), "r"(b0), "r"(b1));
}
#define SWZ128(o) ((o) ^ (((o) >> 3) & 0x70))

#define BK 64
#define TSTG 16384
#define STG (2 * TSTG)            // 32KB per stage
#define NSTAGE 3

// ---------------------------------------------------------------------------
// fp16 single-pass GEMM (R10 proven config).
// epi 0: g0 -> relu+eps fp16 O0 ; g1 -> raw fp16 O1. epi 1: +bias fp32 O0.
// ---------------------------------------------------------------------------
__global__ __launch_bounds__(256, 2)
void mma_gemm(const __half* __restrict__ A, const __half* __restrict__ B,
              void* __restrict__ O0, void* __restrict__ O1,
              const float* __restrict__ bias, int epi)
{
    extern __shared__ __align__(1024) char smraw[];
    const uint32_t sb = smem_u32(smraw);

    const int tid = threadIdx.x;
    const int wid = tid >> 5, lid = tid & 31;
    const int bm = blockIdx.y, bn = blockIdx.x;

    const int wm = (wid & 1) * 64;
    const int wn = (wid >> 1) * 32;
    const int lr = lid & 15, lc = lid >> 4;

    float acc[4][4][4];
    #pragma unroll
    for (int i = 0; i < 4; ++i)
        #pragma unroll
        for (int j = 0; j < 4; ++j)
            #pragma unroll
            for (int r = 0; r < 4; ++r) acc[i][j][r] = 0.f;

    auto load_stage = [&](int kc, int st) {
        const uint32_t base = sb + st * STG;
        const int kofs = kc * BK;
        #pragma unroll
        for (int i = 0; i < 4; ++i) {
            const int idx = i * 256 + tid;
            const int r = idx >> 3, c = idx & 7;
            const uint32_t so = SWZ128(r * 128 + c * 16);
            cpa16(base + so,        A + (size_t)(bm * 128 + r) * 1024 + kofs + c * 8);
            cpa16(base + TSTG + so, B + (size_t)(bn * 128 + r) * 1024 + kofs + c * 8);
        }
        asm volatile("cp.async.commit_group;" ::: "memory");
    };

    auto compute = [&](int st) {
        const uint32_t base = sb + st * STG;
        #pragma unroll
        for (int ks = 0; ks < 4; ++ks) {
            uint32_t af[4][4], bf[2][4];
            #pragma unroll
            for (int mi = 0; mi < 4; ++mi)
                ldmx4(af[mi], base + SWZ128((wm + mi * 16 + lr) * 128 +
                                            ks * 32 + lc * 16));
            #pragma unroll
            for (int nj = 0; nj < 2; ++nj)
                ldmx4(bf[nj], base + TSTG + SWZ128((wn + nj * 16 + lr) * 128 +
                                                   ks * 32 + lc * 16));
            #pragma unroll
            for (int mi = 0; mi < 4; ++mi)
                #pragma unroll
                for (int ni = 0; ni < 4; ++ni) {
                    const int nj = ni >> 1, s = ni & 1;
                    mma16816(acc[mi][ni], af[mi], bf[nj][s], bf[nj][s + 2]);
                }
        }
    };

    load_stage(0, 0);
    load_stage(1, 1);

    const int NK = 1024 / BK;
    int st = 0;
    for (int kc = 0; kc < NK; ++kc) {
        if (kc < NK - 1)
            asm volatile("cp.async.wait_group 1;" ::: "memory");
        else
            asm volatile("cp.async.wait_group 0;" ::: "memory");
        __syncthreads();
        if (kc + 2 < NK) load_stage(kc + 2, (st + 2) % NSTAGE);
        compute(st);
        st = (st + 1) % NSTAGE;
    }

    const int qrow = lid >> 2;
    const int qcol = (lid & 3) * 2;
    const int g = (bn * 128) >> 10;
    const int ncol0 = (epi == 1) ? bn * 128 : (bn * 128) & 1023;

    if (epi == 0) {
        __half* Obase = (__half*)(g == 0 ? O0 : O1);
        const bool do_relu = (g == 0);
        #pragma unroll
        for (int mi = 0; mi < 4; ++mi)
            #pragma unroll
            for (int ni = 0; ni < 4; ++ni) {
                const int cn = ncol0 + wn + ni * 8 + qcol;
                #pragma unroll
                for (int half = 0; half < 2; ++half) {
                    const int gm = bm * 128 + wm + mi * 16 + qrow + half * 8;
                    float v0 = acc[mi][ni][half * 2 + 0];
                    float v1 = acc[mi][ni][half * 2 + 1];
                    if (do_relu) {
                        v0 = fmaxf(v0, 0.f) + EPS;
                        v1 = fmaxf(v1, 0.f) + EPS;
                    }
                    *(__half2*)(Obase + (size_t)gm * 1024 + cn) =
                        __floats2half2_rn(v0, v1);
                }
            }
    } else {
        float* Obase = (float*)O0;
        #pragma unroll
        for (int mi = 0; mi < 4; ++mi)
            #pragma unroll
            for (int ni = 0; ni < 4; ++ni) {
                const int cn = ncol0 + wn + ni * 8 + qcol;
                #pragma unroll
                for (int half = 0; half < 2; ++half) {
                    const int gm = bm * 128 + wm + mi * 16 + qrow + half * 8;
                    const float2 bb = *(const float2*)(bias + cn);
                    *(float2*)(Obase + (size_t)gm * 1024 + cn) =
                        make_float2(acc[mi][ni][half * 2 + 0] + bb.x,
                                    acc[mi][ni][half * 2 + 1] + bb.y);
                }
            }
    }
}

// ---------------------------------------------------------------------------
// fused q-GEMM + z + att + depthwise conv. Grid (8, 128), 256 thr.
// CTA: rows bm*128 (batch b=bm>>5, image rows y0=(bm&31)*2, y0+1),
// q-cols [bn*128,+128) = heads 2bn, 2bn+1.
// Phases: q=x@WqT -> q(relu+eps) to smem; conv(v) to smem fp32; z per row;
// att via mma; out = fp16(att*z + conv) -> Oatt.
// smem: 3*32KB stages (mainloop) reused as Q(32K)+KT(16K)+CONV(64K) = 112KB.
// ---------------------------------------------------------------------------
__global__ __launch_bounds__(256, 2)
void mma_gemm_qatt(const __half* __restrict__ A, const __half* __restrict__ B,
                   const __half* __restrict__ kvt, const float* __restrict__ km,
                   const __half* __restrict__ v, const float* __restrict__ dw,
                   const float* __restrict__ db, __half* __restrict__ Oatt)
{
    extern __shared__ __align__(1024) char smraw[];
    __shared__ float kms[2][64];
    __shared__ float zs[2][128];
    const uint32_t sb = smem_u32(smraw);

    const int tid = threadIdx.x;
    const int wid = tid >> 5, lid = tid & 31;
    const int bm = blockIdx.y, bn = blockIdx.x;
    const int b = bm >> 5;

    const int wm = (wid & 1) * 64;
    const int wn = (wid >> 1) * 32;
    const int lr = lid & 15, lc = lid >> 4;

    float acc[4][4][4];
    #pragma unroll
    for (int i = 0; i < 4; ++i)
        #pragma unroll
        for (int j = 0; j < 4; ++j)
            #pragma unroll
            for (int r = 0; r < 4; ++r) acc[i][j][r] = 0.f;

    auto load_stage = [&](int kc, int st) {
        const uint32_t base = sb + st * STG;
        const int kofs = kc * BK;
        #pragma unroll
        for (int i = 0; i < 4; ++i) {
            const int idx = i * 256 + tid;
            const int r = idx >> 3, c = idx & 7;
            const uint32_t so = SWZ128(r * 128 + c * 16);
            cpa16(base + so,        A + (size_t)(bm * 128 + r) * 1024 + kofs + c * 8);
            cpa16(base + TSTG + so, B + (size_t)(bn * 128 + r) * 1024 + kofs + c * 8);
        }
        asm volatile("cp.async.commit_group;" ::: "memory");
    };

    auto compute = [&](int st) {
        const uint32_t base = sb + st * STG;
        #pragma unroll
        for (int ks = 0; ks < 4; ++ks) {
            uint32_t af[4][4], bf[2][4];
            #pragma unroll
            for (int mi = 0; mi < 4; ++mi)
                ldmx4(af[mi], base + SWZ128((wm + mi * 16 + lr) * 128 +
                                            ks * 32 + lc * 16));
            #pragma unroll
            for (int nj = 0; nj < 2; ++nj)
                ldmx4(bf[nj], base + TSTG + SWZ128((wn + nj * 16 + lr) * 128 +
                                                   ks * 32 + lc * 16));
            #pragma unroll
            for (int mi = 0; mi < 4; ++mi)
                #pragma unroll
                for (int ni = 0; ni < 4; ++ni) {
                    const int nj = ni >> 1, s = ni & 1;
                    mma16816(acc[mi][ni], af[mi], bf[nj][s], bf[nj][s + 2]);
                }
        }
    };

    load_stage(0, 0);
    load_stage(1, 1);

    const int NK = 1024 / BK;
    int st = 0;
    for (int kc = 0; kc < NK; ++kc) {
        if (kc < NK - 1)
            asm volatile("cp.async.wait_group 1;" ::: "memory");
        else
            asm volatile("cp.async.wait_group 0;" ::: "memory");
        __syncthreads();
        if (kc + 2 < NK) load_stage(kc + 2, (st + 2) % NSTAGE);
        compute(st);
        st = (st + 1) % NSTAGE;
    }
    __syncthreads();   // stage buffers dead from here

    // smem overlay: Q0(16K) Q1(16K) | KT0(8K) KT1(8K) | CONV fp32 (64K)
    const uint32_t Q0 = sb, KT0 = sb + 32768;
    float* convs = (float*)(smraw + 49152);   // [128 rows][128 chans]

    // async-load kvt tiles for heads 2bn, 2bn+1
    #pragma unroll
    for (int i = 0; i < 4; ++i) {
        const int idx = i * 256 + tid;
        const int head = idx >> 9;
        const int wi = idx & 511;
        const int r = wi >> 3, c = wi & 7;
        cpa16(KT0 + head * 8192 + SWZ128(r * 128 + c * 16),
              kvt + ((size_t)(b * 16 + 2 * bn + head)) * 4096 + r * 64 + c * 8);
    }
    asm volatile("cp.async.commit_group;" ::: "memory");
    if (tid < 128)
        kms[tid >> 6][tid & 63] =
            km[b * 1024 + (2 * bn + (tid >> 6)) * 64 + (tid & 63)];

    // store q (relu+eps) to smem head tiles
    const int qrow = lid >> 2;
    const int qcol = (lid & 3) * 2;
    #pragma unroll
    for (int mi = 0; mi < 4; ++mi)
        #pragma unroll
        for (int ni = 0; ni < 4; ++ni) {
            const int col = wn + ni * 8 + qcol;
            const int hsel = col >> 6;
            const int c64 = col & 63;
            #pragma unroll
            for (int half = 0; half < 2; ++half) {
                const int rowl = wm + mi * 16 + qrow + half * 8;
                const float v0 = fmaxf(acc[mi][ni][half * 2 + 0], 0.f) + EPS;
                const float v1 = fmaxf(acc[mi][ni][half * 2 + 1], 0.f) + EPS;
                *(__half2*)(smraw + hsel * 16384 + SWZ128(rowl * 128 + c64 * 2)) =
                    __floats2half2_rn(v0, v1);
            }
        }
    __syncthreads();

    // ---- depthwise conv for this CTA's (2 y-rows) x (128 chans) ----
    // thread: chan c = tid&127 (head=c>>6, d=c&63), y-row = y0 + (tid>>7)
    {
        const int c = tid & 127;
        const int d = c & 63;
        const int h = 2 * bn + (c >> 6);
        const int y = (bm & 31) * 2 + (tid >> 7);
        float wgt[25];
        #pragma unroll
        for (int i = 0; i < 25; ++i) wgt[i] = dw[d * 25 + i];
        const float bias = db[d];
        const __half* vb = v + (size_t)b * 4096 * 1024 + h * 64 + d;

        float win[5][5];
        #pragma unroll
        for (int r = 0; r < 5; ++r) {
            const int yy = y - 2 + r;
            #pragma unroll
            for (int cc = 0; cc < 4; ++cc) {
                const int xx = cc - 2;   // x=0 window cols -2..2 -> cc 0..4
                win[r][cc + 1] = (yy >= 0 && yy < 64 && xx >= 0)
                    ? __half2float(vb[(size_t)(yy * 64 + xx) * 1024]) : 0.f;
            }
            win[r][0] = 0.f;   // x=-2 always OOB at x=0
        }
        const int rowbase = (tid >> 7) * 64;
        #pragma unroll 4
        for (int x = 0; x < 64; ++x) {
            // shift in column x+2
            #pragma unroll
            for (int r = 0; r < 5; ++r) {
                #pragma unroll
                for (int cc = 0; cc < 4; ++cc) win[r][cc] = win[r][cc + 1];
                const int yy = y - 2 + r;
                const int xx = x + 2;
                win[r][4] = (yy >= 0 && yy < 64 && xx < 64)
                    ? __half2float(vb[(size_t)(yy * 64 + xx) * 1024]) : 0.f;
            }
            float acc3 = bias;
            #pragma unroll
            for (int r = 0; r < 5; ++r)
                #pragma unroll
                for (int cc = 0; cc < 5; ++cc)
                    acc3 = fmaf(win[r][cc], wgt[r * 5 + cc], acc3);
            convs[(rowbase + x) * 128 + c] = acc3;
        }
    }

    // z per (head,row)
    {
        const int row = tid >> 1, head = tid & 1;
        const char* qt = smraw + head * 16384;
        float zd = EPS;
        #pragma unroll
        for (int dd = 0; dd < 64; dd += 4) {
            const uint2 qd = *(const uint2*)(qt + SWZ128(row * 128 + dd * 2));
            const __half2* qh = (const __half2*)&qd;
            const float2 f0 = __half22float2(qh[0]);
            const float2 f1 = __half22float2(qh[1]);
            zd = fmaf(f0.x, kms[head][dd + 0], zd);
            zd = fmaf(f0.y, kms[head][dd + 1], zd);
            zd = fmaf(f1.x, kms[head][dd + 2], zd);
            zd = fmaf(f1.y, kms[head][dd + 3], zd);
        }
        zs[head][row] = 1.0f / zd;
    }
    asm volatile("cp.async.wait_group 0;" ::: "memory");
    __syncthreads();

    // att mma: warp -> head = wid&1, rows mrow..mrow+31
    const int head = wid & 1;
    const int mrow = (wid >> 1) * 32;
    const uint32_t qt = Q0 + head * 16384;
    const uint32_t kt = KT0 + head * 8192;

    float acc2[2][8][4];
    #pragma unroll
    for (int i = 0; i < 2; ++i)
        #pragma unroll
        for (int j = 0; j < 8; ++j)
            #pragma unroll
            for (int r = 0; r < 4; ++r) acc2[i][j][r] = 0.f;

    #pragma unroll
    for (int kk = 0; kk < 4; ++kk) {
        uint32_t af[2][4], bf[4][4];
        #pragma unroll
        for (int mi = 0; mi < 2; ++mi)
            ldmx4(af[mi], qt + SWZ128((mrow + mi * 16 + lr) * 128 +
                                      kk * 32 + lc * 16));
        #pragma unroll
        for (int nj = 0; nj < 4; ++nj)
            ldmx4(bf[nj], kt + SWZ128((nj * 16 + lr) * 128 + kk * 32 + lc * 16));
        #pragma unroll
        for (int mi = 0; mi < 2; ++mi)
            #pragma unroll
            for (int ni = 0; ni < 8; ++ni) {
                const int nj = ni >> 1, s = ni & 1;
                mma16816(acc2[mi][ni], af[mi], bf[nj][s], bf[nj][s + 2]);
            }
    }

    #pragma unroll
    for (int mi = 0; mi < 2; ++mi)
        #pragma unroll
        for (int ni = 0; ni < 8; ++ni) {
            const int e = ni * 8 + qcol;
            #pragma unroll
            for (int half = 0; half < 2; ++half) {
                const int rowl = mrow + mi * 16 + qrow + half * 8;
                const float z = zs[head][rowl];
                const float c0 = convs[rowl * 128 + head * 64 + e];
                const float c1 = convs[rowl * 128 + head * 64 + e + 1];
                const size_t go = (size_t)(bm * 128 + rowl) * 1024 +
                                  bn * 128 + head * 64 + e;
                *(__half2*)(Oatt + go) =
                    __floats2half2_rn(acc2[mi][ni][half * 2 + 0] * z + c0,
                                      acc2[mi][ni][half * 2 + 1] * z + c1);
            }
        }
}

// ---------------------------------------------------------------------------
// prep: fused x->fp16 + 3 weight transpose/converts in ONE launch.
// ---------------------------------------------------------------------------
__global__ __launch_bounds__(256)
void prep_kernel(const float4* __restrict__ X, __half2* __restrict__ H,
                 const float* __restrict__ Wq, const float* __restrict__ Wkv,
                 const float* __restrict__ Wproj, __half* __restrict__ w16)
{
    const int bx = blockIdx.x;
    const int tid = threadIdx.x;

    if (bx < 16384) {
        const int i = bx * 256 + tid;
        float4 v = X[i];
        H[2 * i]     = __floats2half2_rn(v.x, v.y);
        H[2 * i + 1] = __floats2half2_rn(v.z, v.w);
        return;
    }

    __shared__ float t[32][33];
    const float* W;
    __half* T;
    int N, bidx;
    if (bx < 17408)      { W = Wq;    T = w16;           N = 1024; bidx = bx - 16384; }
    else if (bx < 19456) { W = Wkv;   T = w16 + 1048576; N = 2048; bidx = bx - 17408; }
    else                 { W = Wproj; T = w16 + 3145728; N = 1024; bidx = bx - 19456; }

    const int nb = N / 32;
    const int n0 = (bidx % nb) * 32;
    const int k0 = (bidx / nb) * 32;
    const int tx = tid & 31, ty = tid >> 5;

    #pragma unroll
    for (int i = 0; i < 32; i += 8)
        t[ty + i][tx] = W[(size_t)(k0 + ty + i) * N + n0 + tx];
    __syncthreads();
    #pragma unroll
    for (int i = 0; i < 32; i += 8)
        T[(size_t)(n0 + ty + i) * 1024 + k0 + tx] = __float2half_rn(t[tx][ty + i]);
}

// ---------------------------------------------------------------------------
// kv partials (8 n-chunks of 512) + fused k-sums + last-block reduction
// ---------------------------------------------------------------------------
#define KVT 8192

__global__ __launch_bounds__(128)
void kvmat_mma(const __half* __restrict__ k, const __half* __restrict__ v,
               float* __restrict__ kvp, float* __restrict__ kmp,
               __half* __restrict__ kvt, float* __restrict__ km)
{
    __shared__ __align__(1024) char kvs_raw[4 * KVT];
    __shared__ float sks[2][64];
    __shared__ int is_last;
    const uint32_t sb = smem_u32(kvs_raw);

    const int tid = threadIdx.x;
    const int wid = tid >> 5, lid = tid & 31;
    const int nc = blockIdx.x, h = blockIdx.y, b = blockIdx.z;
    const int bh = b * 16 + h;

    const size_t base = ((size_t)(b * 4096 + nc * 512)) * 1024 + h * 64;

    auto load_sc = [&](int sc, int buf) {
        const uint32_t kb = sb + buf * 2 * KVT;
        #pragma unroll
        for (int i = 0; i < 4; ++i) {
            const int idx = i * 128 + tid;
            const int r = idx >> 3, c = idx & 7;
            const size_t go = base + (size_t)(sc * 64 + r) * 1024 + c * 8;
            const uint32_t so = SWZ128(r * 128 + c * 16);
            cpa16(kb + so, k + go);
            cpa16(kb + KVT + so, v + go);
        }
        asm volatile("cp.async.commit_group;" ::: "memory");
    };

    float acc[8][4];
    #pragma unroll
    for (int i = 0; i < 8; ++i)
        #pragma unroll
        for (int r = 0; r < 4; ++r) acc[i][r] = 0.f;
    float ks_acc = 0.f;

    const int se = tid & 63;
    const int srg = tid >> 6;
    const int trow  = ((lid >> 4) << 3) + (lid & 7);
    const int tcolh = ((lid >> 3) & 1) << 3;

    load_sc(0, 0);
    for (int sc = 0; sc < 8; ++sc) {
        const int buf = sc & 1;
        if (sc < 7) {
            load_sc(sc + 1, buf ^ 1);
            asm volatile("cp.async.wait_group 1;" ::: "memory");
        } else {
            asm volatile("cp.async.wait_group 0;" ::: "memory");
        }
        __syncthreads();
        const uint32_t kb = sb + buf * 2 * KVT;
        #pragma unroll
        for (int ks = 0; ks < 4; ++ks) {
            uint32_t af[4], bf[4][4];
            ldmx4t(af, kb + SWZ128((ks * 16 + trow) * 128 +
                                   (wid * 16 + tcolh) * 2));
            #pragma unroll
            for (int nj = 0; nj < 4; ++nj)
                ldmx4t(bf[nj], kb + KVT + SWZ128((ks * 16 + trow) * 128 +
                                                 (nj * 16 + tcolh) * 2));
            #pragma unroll
            for (int ni = 0; ni < 8; ++ni) {
                const int nj = ni >> 1, s = ni & 1;
                mma16816(acc[ni], af, bf[nj][s], bf[nj][s + 2]);
            }
        }
        #pragma unroll 8
        for (int rr = 0; rr < 32; ++rr) {
            const int row = srg * 32 + rr;
            const __half kv16 = *(const __half*)
                ((char*)kvs_raw + buf * 2 * KVT + SWZ128(row * 128 + se * 2));
            ks_acc += __half2float(kv16);
        }
        __syncthreads();
    }
    sks[srg][se] = ks_acc;

    const int qrow = lid >> 2;
    const int qcol = (lid & 3) * 2;
    float* kvo = kvp + (((size_t)(nc * 4 + b)) * 16 + h) * 4096;
    #pragma unroll
    for (int ni = 0; ni < 8; ++ni)
        #pragma unroll
        for (int half = 0; half < 2; ++half) {
            const int dm = wid * 16 + qrow + half * 8;
            *(float2*)(kvo + dm * 64 + ni * 8 + qcol) =
                make_float2(acc[ni][half * 2 + 0], acc[ni][half * 2 + 1]);
        }
    __syncthreads();
    if (tid < 64)
        kmp[(size_t)(nc * 4 + b) * 1024 + h * 64 + tid] =
            sks[0][tid] + sks[1][tid];

    // last-block reduction: 8 partials -> kvt fp16 + km
    __threadfence();
    if (tid == 0)
        is_last = (atomicAdd(&g_cnt[bh], 1) == 7);
    __syncthreads();
    if (!is_last) return;
    __threadfence();

    for (int i = tid; i < 4096; i += 128) {
        float s = 0.f;
        #pragma unroll
        for (int c = 0; c < 8; ++c)
            s += kvp[(((size_t)(c * 4 + b)) * 16 + h) * 4096 + i];
        const int d = i >> 6, e = i & 63;
        kvt[(size_t)bh * 4096 + e * 64 + d] = __float2half_rn(s * (1.0f / 4096.0f));
    }
    if (tid < 64) {
        float s = 0.f;
        #pragma unroll
        for (int c = 0; c < 8; ++c)
            s += kmp[(size_t)(c * 4 + b) * 1024 + h * 64 + tid];
        km[b * 1024 + h * 64 + tid] = s * (1.0f / 4096.0f);
    }
    if (tid == 0) atomicExch(&g_cnt[bh], 0);
}

// ---------------------------------------------------------------------------
extern "C" void kernel_launch(void* const* d_in, const int* in_sizes, int n_in,
                              void* d_out, int out_size)
{
    const float* x     = (const float*)d_in[0];
    const float* Wq    = (const float*)d_in[1];
    const float* Wkv   = (const float*)d_in[2];
    const float* Wproj = (const float*)d_in[3];
    const float* bproj = (const float*)d_in[4];
    const float* dwc_w = (const float*)d_in[5];
    const float* dwc_b = (const float*)d_in[6];
    float* out = (float*)d_out;

    float *km, *kvp, *kmp;
    __half *q16, *k16, *v16, *a16, *w16, *kvt16;
    cudaGetSymbolAddress((void**)&q16,   g_q16);
    cudaGetSymbolAddress((void**)&k16,   g_k16);
    cudaGetSymbolAddress((void**)&v16,   g_v16);
    cudaGetSymbolAddress((void**)&km,    g_kmean);
    cudaGetSymbolAddress((void**)&kvt16, g_kvt16);
    cudaGetSymbolAddress((void**)&kvp,   g_kvp);
    cudaGetSymbolAddress((void**)&kmp,   g_kmp);
    cudaGetSymbolAddress((void**)&a16,   g_a16);
    cudaGetSymbolAddress((void**)&w16,   g_w16);

    cudaFuncSetAttribute(mma_gemm, cudaFuncAttributeMaxDynamicSharedMemorySize,
                         NSTAGE * STG);
    cudaFuncSetAttribute(mma_gemm_qatt,
                         cudaFuncAttributeMaxDynamicSharedMemorySize, 114688);

    const size_t smem = NSTAGE * STG;

    // 1: fused conversions
    prep_kernel<<<20480, 256>>>((const float4*)x, (__half2*)a16,
                                Wq, Wkv, Wproj, w16);
    // 2: k/v GEMM (N=2048): k relu->k16, v raw->v16
    mma_gemm<<<dim3(16, 128), 256, smem>>>(a16, w16 + 1048576, k16, v16,
                                           nullptr, 0);
    // 3: kv matrices + kmean (+ fused final reduction -> kvt16, km)
    kvmat_mma<<<dim3(8, 16, 4), 128>>>(k16, v16, kvp, kmp, kvt16, km);
    // 4: fused q GEMM + z + att + conv -> q16
    mma_gemm_qatt<<<dim3(8, 128), 256, 114688>>>(a16, w16, kvt16, km,
                                                 v16, dwc_w, dwc_b, q16);
    // 5: out = (att+conv) @ Wproj + bproj
    mma_gemm<<<dim3(8, 128), 256, smem>>>(q16, w16 + 3145728, out, nullptr,
                                          bproj, 1);
}

// round 15
// speedup vs baseline: 1.1517x; 1.1517x over previous
#include <cuda_runtime.h>
#include <cuda_fp16.h>
#include <cstdint>

#define EPS 1e-6f

// ---------------- scratch (__device__ globals; no allocations allowed) -----
__device__ __half g_q16[16777216];   // att+conv result fp16 (A of GEMM2)
__device__ __half g_k16[16777216];
__device__ __half g_v16[16777216];
__device__ __half g_c16[16777216];   // conv output fp16
__device__ float g_kmean[4096];      // (B,1024)
__device__ __half g_kvt16[262144];   // kv^T fp16: [b,h][e][d]
__device__ float g_kvp[2097152];     // kv partials: [8 nc][B][h][64][64]
__device__ float g_kmp[32768];       // kmean partials: [8 nc][B][1024]
__device__ __half g_a16[16777216];   // x fp16
__device__ __half g_w16[4194304];    // transposed weights fp16 [WqT|WkvT|WprojT]
__device__ int g_cnt[64];            // kvmat finisher counters

// ---------------- PTX helpers ----------------------------------------------
__device__ __forceinline__ uint32_t smem_u32(const void* p) {
    uint32_t a;
    asm("{ .reg .u64 t; cvta.to.shared.u64 t, %1; cvt.u32.u64 %0, t; }"
        : "=r"(a) : "l"(p));
    return a;
}
__device__ __forceinline__ void cpa16(uint32_t s, const void* g) {
    asm volatile("cp.async.cg.shared.global [%0], [%1], 16;" :: "r"(s), "l"(g));
}
__device__ __forceinline__ void ldmx4(uint32_t* r, uint32_t a) {
    asm volatile("ldmatrix.sync.aligned.m8n8.x4.shared.b16 {%0,%1,%2,%3}, [%4];"
                 : "=r"(r[0]), "=r"(r[1]), "=r"(r[2]), "=r"(r[3]) : "r"(a));
}
__device__ __forceinline__ void ldmx4t(uint32_t* r, uint32_t a) {
    asm volatile("ldmatrix.sync.aligned.m8n8.x4.trans.shared.b16 {%0,%1,%2,%3}, [%4];"
                 : "=r"(r[0]), "=r"(r[1]), "=r"(r[2]), "=r"(r[3]) : "r"(a));
}
__device__ __forceinline__ void mma16816(float* c, const uint32_t* a,
                                         uint32_t b0, uint32_t b1) {
    asm volatile(
        "mma.sync.aligned.m16n8k16.row.col.f32.f16.f16.f32 "
        "{%0,%1,%2,%3},{%4,%5,%6,%7},{%8,%9},{%0,%1,%2,%3};"
        : "+f"(c[0]), "+f"(c[1]), "+f"(c[2]), "+f"(c[3])
        : "r"(a[0]), "r"(a[1]), "r"(a[2]), "r"(a[3]), "r"(b0), "r"(b1));
}
#define SWZ128(o) ((o) ^ (((o) >> 3) & 0x70))
#define GDC_WAIT()   asm volatile("griddepcontrol.wait;" ::: "memory")
#define GDC_LAUNCH() asm volatile("griddepcontrol.launch_dependents;" ::: "memory")

#define BK 64
#define TSTG 16384
#define STG (2 * TSTG)            // 32KB per stage
#define NSTAGE 3

// ---------------------------------------------------------------------------
// fp16 single-pass GEMM (R10/R13 proven config). PDL: wait at entry,
// launch_dependents after mainloop.
// epi 0: g0 -> relu+eps fp16 O0 ; g1 -> raw fp16 O1. epi 1: +bias fp32 O0.
// ---------------------------------------------------------------------------
__global__ __launch_bounds__(256, 2)
void mma_gemm(const __half* __restrict__ A, const __half* __restrict__ B,
              void* __restrict__ O0, void* __restrict__ O1,
              const float* __restrict__ bias, int epi)
{
    extern __shared__ __align__(1024) char smraw[];
    const uint32_t sb = smem_u32(smraw);

    const int tid = threadIdx.x;
    const int wid = tid >> 5, lid = tid & 31;
    const int bm = blockIdx.y, bn = blockIdx.x;

    const int wm = (wid & 1) * 64;
    const int wn = (wid >> 1) * 32;
    const int lr = lid & 15, lc = lid >> 4;

    float acc[4][4][4];
    #pragma unroll
    for (int i = 0; i < 4; ++i)
        #pragma unroll
        for (int j = 0; j < 4; ++j)
            #pragma unroll
            for (int r = 0; r < 4; ++r) acc[i][j][r] = 0.f;

    auto load_stage = [&](int kc, int st) {
        const uint32_t base = sb + st * STG;
        const int kofs = kc * BK;
        #pragma unroll
        for (int i = 0; i < 4; ++i) {
            const int idx = i * 256 + tid;
            const int r = idx >> 3, c = idx & 7;
            const uint32_t so = SWZ128(r * 128 + c * 16);
            cpa16(base + so,        A + (size_t)(bm * 128 + r) * 1024 + kofs + c * 8);
            cpa16(base + TSTG + so, B + (size_t)(bn * 128 + r) * 1024 + kofs + c * 8);
        }
        asm volatile("cp.async.commit_group;" ::: "memory");
    };

    auto compute = [&](int st) {
        const uint32_t base = sb + st * STG;
        #pragma unroll
        for (int ks = 0; ks < 4; ++ks) {
            uint32_t af[4][4], bf[2][4];
            #pragma unroll
            for (int mi = 0; mi < 4; ++mi)
                ldmx4(af[mi], base + SWZ128((wm + mi * 16 + lr) * 128 +
                                            ks * 32 + lc * 16));
            #pragma unroll
            for (int nj = 0; nj < 2; ++nj)
                ldmx4(bf[nj], base + TSTG + SWZ128((wn + nj * 16 + lr) * 128 +
                                                   ks * 32 + lc * 16));
            #pragma unroll
            for (int mi = 0; mi < 4; ++mi)
                #pragma unroll
                for (int ni = 0; ni < 4; ++ni) {
                    const int nj = ni >> 1, s = ni & 1;
                    mma16816(acc[mi][ni], af[mi], bf[nj][s], bf[nj][s + 2]);
                }
        }
    };

    GDC_WAIT();
    load_stage(0, 0);
    load_stage(1, 1);

    const int NK = 1024 / BK;
    int st = 0;
    for (int kc = 0; kc < NK; ++kc) {
        if (kc < NK - 1)
            asm volatile("cp.async.wait_group 1;" ::: "memory");
        else
            asm volatile("cp.async.wait_group 0;" ::: "memory");
        __syncthreads();
        if (kc + 2 < NK) load_stage(kc + 2, (st + 2) % NSTAGE);
        compute(st);
        st = (st + 1) % NSTAGE;
    }
    GDC_LAUNCH();

    const int qrow = lid >> 2;
    const int qcol = (lid & 3) * 2;
    const int g = (bn * 128) >> 10;
    const int ncol0 = (epi == 1) ? bn * 128 : (bn * 128) & 1023;

    if (epi == 0) {
        __half* Obase = (__half*)(g == 0 ? O0 : O1);
        const bool do_relu = (g == 0);
        #pragma unroll
        for (int mi = 0; mi < 4; ++mi)
            #pragma unroll
            for (int ni = 0; ni < 4; ++ni) {
                const int cn = ncol0 + wn + ni * 8 + qcol;
                #pragma unroll
                for (int half = 0; half < 2; ++half) {
                    const int gm = bm * 128 + wm + mi * 16 + qrow + half * 8;
                    float v0 = acc[mi][ni][half * 2 + 0];
                    float v1 = acc[mi][ni][half * 2 + 1];
                    if (do_relu) {
                        v0 = fmaxf(v0, 0.f) + EPS;
                        v1 = fmaxf(v1, 0.f) + EPS;
                    }
                    *(__half2*)(Obase + (size_t)gm * 1024 + cn) =
                        __floats2half2_rn(v0, v1);
                }
            }
    } else {
        float* Obase = (float*)O0;
        #pragma unroll
        for (int mi = 0; mi < 4; ++mi)
            #pragma unroll
            for (int ni = 0; ni < 4; ++ni) {
                const int cn = ncol0 + wn + ni * 8 + qcol;
                #pragma unroll
                for (int half = 0; half < 2; ++half) {
                    const int gm = bm * 128 + wm + mi * 16 + qrow + half * 8;
                    const float2 bb = *(const float2*)(bias + cn);
                    *(float2*)(Obase + (size_t)gm * 1024 + cn) =
                        make_float2(acc[mi][ni][half * 2 + 0] + bb.x,
                                    acc[mi][ni][half * 2 + 1] + bb.y);
                }
            }
    }
}

// ---------------------------------------------------------------------------
// fused q-GEMM + z + att (R13 proven). PDL: NO entry wait (mainloop reads
// only prep outputs, transitively complete); wait AFTER mainloop, before
// kvt/km/c16; launch_dependents after mainloop.
// ---------------------------------------------------------------------------
__global__ __launch_bounds__(256, 2)
void mma_gemm_qatt(const __half* __restrict__ A, const __half* __restrict__ B,
                   const __half* __restrict__ kvt, const float* __restrict__ km,
                   const __half* __restrict__ c16, __half* __restrict__ Oatt)
{
    extern __shared__ __align__(1024) char smraw[];
    __shared__ float kms[2][64];
    __shared__ float zs[2][128];
    const uint32_t sb = smem_u32(smraw);

    const int tid = threadIdx.x;
    const int wid = tid >> 5, lid = tid & 31;
    const int bm = blockIdx.y, bn = blockIdx.x;
    const int b = bm >> 5;

    const int wm = (wid & 1) * 64;
    const int wn = (wid >> 1) * 32;
    const int lr = lid & 15, lc = lid >> 4;

    float acc[4][4][4];
    #pragma unroll
    for (int i = 0; i < 4; ++i)
        #pragma unroll
        for (int j = 0; j < 4; ++j)
            #pragma unroll
            for (int r = 0; r < 4; ++r) acc[i][j][r] = 0.f;

    auto load_stage = [&](int kc, int st) {
        const uint32_t base = sb + st * STG;
        const int kofs = kc * BK;
        #pragma unroll
        for (int i = 0; i < 4; ++i) {
            const int idx = i * 256 + tid;
            const int r = idx >> 3, c = idx & 7;
            const uint32_t so = SWZ128(r * 128 + c * 16);
            cpa16(base + so,        A + (size_t)(bm * 128 + r) * 1024 + kofs + c * 8);
            cpa16(base + TSTG + so, B + (size_t)(bn * 128 + r) * 1024 + kofs + c * 8);
        }
        asm volatile("cp.async.commit_group;" ::: "memory");
    };

    auto compute = [&](int st) {
        const uint32_t base = sb + st * STG;
        #pragma unroll
        for (int ks = 0; ks < 4; ++ks) {
            uint32_t af[4][4], bf[2][4];
            #pragma unroll
            for (int mi = 0; mi < 4; ++mi)
                ldmx4(af[mi], base + SWZ128((wm + mi * 16 + lr) * 128 +
                                            ks * 32 + lc * 16));
            #pragma unroll
            for (int nj = 0; nj < 2; ++nj)
                ldmx4(bf[nj], base + TSTG + SWZ128((wn + nj * 16 + lr) * 128 +
                                                   ks * 32 + lc * 16));
            #pragma unroll
            for (int mi = 0; mi < 4; ++mi)
                #pragma unroll
                for (int ni = 0; ni < 4; ++ni) {
                    const int nj = ni >> 1, s = ni & 1;
                    mma16816(acc[mi][ni], af[mi], bf[nj][s], bf[nj][s + 2]);
                }
        }
    };

    load_stage(0, 0);
    load_stage(1, 1);

    const int NK = 1024 / BK;
    int st = 0;
    for (int kc = 0; kc < NK; ++kc) {
        if (kc < NK - 1)
            asm volatile("cp.async.wait_group 1;" ::: "memory");
        else
            asm volatile("cp.async.wait_group 0;" ::: "memory");
        __syncthreads();
        if (kc + 2 < NK) load_stage(kc + 2, (st + 2) % NSTAGE);
        compute(st);
        st = (st + 1) % NSTAGE;
    }
    GDC_LAUNCH();
    __syncthreads();   // stage buffers free from here

    const uint32_t Q0 = sb, KT0 = sb + 32768;

    // store q (relu+eps) to smem head tiles (independent of predecessors)
    const int qrow = lid >> 2;
    const int qcol = (lid & 3) * 2;
    #pragma unroll
    for (int mi = 0; mi < 4; ++mi)
        #pragma unroll
        for (int ni = 0; ni < 4; ++ni) {
            const int col = wn + ni * 8 + qcol;
            const int hsel = col >> 6;
            const int c64 = col & 63;
            #pragma unroll
            for (int half = 0; half < 2; ++half) {
                const int rowl = wm + mi * 16 + qrow + half * 8;
                const float v0 = fmaxf(acc[mi][ni][half * 2 + 0], 0.f) + EPS;
                const float v1 = fmaxf(acc[mi][ni][half * 2 + 1], 0.f) + EPS;
                *(__half2*)(smraw + hsel * 16384 + SWZ128(rowl * 128 + c64 * 2)) =
                    __floats2half2_rn(v0, v1);
            }
        }

    // wait for kvmat (-> conv -> gemm_kv) before touching kvt/km/c16
    GDC_WAIT();

    #pragma unroll
    for (int i = 0; i < 4; ++i) {
        const int idx = i * 256 + tid;
        const int head = idx >> 9;
        const int wi = idx & 511;
        const int r = wi >> 3, c = wi & 7;
        cpa16(KT0 + head * 8192 + SWZ128(r * 128 + c * 16),
              kvt + ((size_t)(b * 16 + 2 * bn + head)) * 4096 + r * 64 + c * 8);
    }
    asm volatile("cp.async.commit_group;" ::: "memory");
    if (tid < 128)
        kms[tid >> 6][tid & 63] =
            km[b * 1024 + (2 * bn + (tid >> 6)) * 64 + (tid & 63)];
    __syncthreads();

    // z per (head,row)
    {
        const int row = tid >> 1, head = tid & 1;
        const char* qt = smraw + head * 16384;
        float zd = EPS;
        #pragma unroll
        for (int dd = 0; dd < 64; dd += 4) {
            const uint2 qd = *(const uint2*)(qt + SWZ128(row * 128 + dd * 2));
            const __half2* qh = (const __half2*)&qd;
            const float2 f0 = __half22float2(qh[0]);
            const float2 f1 = __half22float2(qh[1]);
            zd = fmaf(f0.x, kms[head][dd + 0], zd);
            zd = fmaf(f0.y, kms[head][dd + 1], zd);
            zd = fmaf(f1.x, kms[head][dd + 2], zd);
            zd = fmaf(f1.y, kms[head][dd + 3], zd);
        }
        zs[head][row] = 1.0f / zd;
    }
    asm volatile("cp.async.wait_group 0;" ::: "memory");
    __syncthreads();

    const int head = wid & 1;
    const int mrow = (wid >> 1) * 32;
    const uint32_t qt = Q0 + head * 16384;
    const uint32_t kt = KT0 + head * 8192;

    float acc2[2][8][4];
    #pragma unroll
    for (int i = 0; i < 2; ++i)
        #pragma unroll
        for (int j = 0; j < 8; ++j)
            #pragma unroll
            for (int r = 0; r < 4; ++r) acc2[i][j][r] = 0.f;

    #pragma unroll
    for (int kk = 0; kk < 4; ++kk) {
        uint32_t af[2][4], bf[4][4];
        #pragma unroll
        for (int mi = 0; mi < 2; ++mi)
            ldmx4(af[mi], qt + SWZ128((mrow + mi * 16 + lr) * 128 +
                                      kk * 32 + lc * 16));
        #pragma unroll
        for (int nj = 0; nj < 4; ++nj)
            ldmx4(bf[nj], kt + SWZ128((nj * 16 + lr) * 128 + kk * 32 + lc * 16));
        #pragma unroll
        for (int mi = 0; mi < 2; ++mi)
            #pragma unroll
            for (int ni = 0; ni < 8; ++ni) {
                const int nj = ni >> 1, s = ni & 1;
                mma16816(acc2[mi][ni], af[mi], bf[nj][s], bf[nj][s + 2]);
            }
    }

    #pragma unroll
    for (int mi = 0; mi < 2; ++mi)
        #pragma unroll
        for (int ni = 0; ni < 8; ++ni) {
            const int e = ni * 8 + qcol;
            #pragma unroll
            for (int half = 0; half < 2; ++half) {
                const int rowl = mrow + mi * 16 + qrow + half * 8;
                const float z = zs[head][rowl];
                const size_t go = (size_t)(bm * 128 + rowl) * 1024 +
                                  bn * 128 + head * 64 + e;
                const float2 cf = __half22float2(*(const __half2*)(c16 + go));
                *(__half2*)(Oatt + go) =
                    __floats2half2_rn(acc2[mi][ni][half * 2 + 0] * z + cf.x,
                                      acc2[mi][ni][half * 2 + 1] * z + cf.y);
            }
        }
}

// ---------------------------------------------------------------------------
// prep: fused x->fp16 + 3 weight transpose/converts in ONE launch.
// ---------------------------------------------------------------------------
__global__ __launch_bounds__(256)
void prep_kernel(const float4* __restrict__ X, __half2* __restrict__ H,
                 const float* __restrict__ Wq, const float* __restrict__ Wkv,
                 const float* __restrict__ Wproj, __half* __restrict__ w16)
{
    const int bx = blockIdx.x;
    const int tid = threadIdx.x;

    if (bx < 16384) {
        const int i = bx * 256 + tid;
        float4 v = X[i];
        H[2 * i]     = __floats2half2_rn(v.x, v.y);
        H[2 * i + 1] = __floats2half2_rn(v.z, v.w);
        return;
    }

    __shared__ float t[32][33];
    const float* W;
    __half* T;
    int N, bidx;
    if (bx < 17408)      { W = Wq;    T = w16;           N = 1024; bidx = bx - 16384; }
    else if (bx < 19456) { W = Wkv;   T = w16 + 1048576; N = 2048; bidx = bx - 17408; }
    else                 { W = Wproj; T = w16 + 3145728; N = 1024; bidx = bx - 19456; }

    const int nb = N / 32;
    const int n0 = (bidx % nb) * 32;
    const int k0 = (bidx / nb) * 32;
    const int tx = tid & 31, ty = tid >> 5;

    #pragma unroll
    for (int i = 0; i < 32; i += 8)
        t[ty + i][tx] = W[(size_t)(k0 + ty + i) * N + n0 + tx];
    __syncthreads();
    #pragma unroll
    for (int i = 0; i < 32; i += 8)
        T[(size_t)(n0 + ty + i) * 1024 + k0 + tx] = __float2half_rn(t[tx][ty + i]);
}

// ---------------------------------------------------------------------------
// depthwise 5x5 SAME conv on fp16 v; writes conv output fp16 to c16.
// PDL: wait at entry (needs v16), launch_dependents right after wait.
// ---------------------------------------------------------------------------
__global__ __launch_bounds__(256)
void conv_kernel(const __half* __restrict__ v, const float* __restrict__ w,
                 const float* __restrict__ wb, __half* __restrict__ c16)
{
    GDC_WAIT();
    GDC_LAUNCH();

    const int e  = threadIdx.x & 63;
    const int xg = threadIdx.x >> 6;
    const int x  = blockIdx.x * 4 + xg;
    const int y0 = blockIdx.y * 8;
    const int bh = blockIdx.z;
    const int b = bh >> 4, h = bh & 15;

    float wgt[25];
    #pragma unroll
    for (int i = 0; i < 25; ++i) wgt[i] = w[e * 25 + i];
    const float bias = wb[e];

    const size_t cofs = (size_t)b * 4096 * 1024 + h * 64 + e;
    const __half* vb = v + cofs;
    __half* cb = c16 + cofs;

    float win[5][5];
    #pragma unroll
    for (int r = 0; r < 4; ++r) {
        const int yy = y0 - 2 + r;
        #pragma unroll
        for (int c = 0; c < 5; ++c) {
            const int xx = x - 2 + c;
            win[r][c] = (yy >= 0 && yy < 64 && xx >= 0 && xx < 64)
                        ? __half2float(vb[(size_t)(yy * 64 + xx) * 1024]) : 0.f;
        }
    }

    #pragma unroll
    for (int oy = 0; oy < 8; ++oy) {
        const int yy = y0 + oy + 2;
        #pragma unroll
        for (int c = 0; c < 5; ++c) {
            const int xx = x - 2 + c;
            win[4][c] = (yy < 64 && xx >= 0 && xx < 64)
                        ? __half2float(vb[(size_t)(yy * 64 + xx) * 1024]) : 0.f;
        }
        float acc = bias;
        #pragma unroll
        for (int r = 0; r < 5; ++r)
            #pragma unroll
            for (int c = 0; c < 5; ++c)
                acc = fmaf(win[r][c], wgt[r * 5 + c], acc);

        cb[(size_t)((y0 + oy) * 64 + x) * 1024] = __float2half_rn(acc);

        #pragma unroll
        for (int r = 0; r < 4; ++r)
            #pragma unroll
            for (int c = 0; c < 5; ++c) win[r][c] = win[r + 1][c];
    }
}

// ---------------------------------------------------------------------------
// kv partials (8 n-chunks of 512) + fused k-sums + last-block reduction.
// PDL: wait at entry (reads k16/v16; predecessor conv done => gemm_kv done),
// launch_dependents right after wait (qatt mainloop is independent).
// ---------------------------------------------------------------------------
#define KVT 8192

__global__ __launch_bounds__(128)
void kvmat_mma(const __half* __restrict__ k, const __half* __restrict__ v,
               float* __restrict__ kvp, float* __restrict__ kmp,
               __half* __restrict__ kvt, float* __restrict__ km)
{
    __shared__ __align__(1024) char kvs_raw[4 * KVT];
    __shared__ float sks[2][64];
    __shared__ int is_last;
    const uint32_t sb = smem_u32(kvs_raw);

    GDC_WAIT();
    GDC_LAUNCH();

    const int tid = threadIdx.x;
    const int wid = tid >> 5, lid = tid & 31;
    const int nc = blockIdx.x, h = blockIdx.y, b = blockIdx.z;
    const int bh = b * 16 + h;

    const size_t base = ((size_t)(b * 4096 + nc * 512)) * 1024 + h * 64;

    auto load_sc = [&](int sc, int buf) {
        const uint32_t kb = sb + buf * 2 * KVT;
        #pragma unroll
        for (int i = 0; i < 4; ++i) {
            const int idx = i * 128 + tid;
            const int r = idx >> 3, c = idx & 7;
            const size_t go = base + (size_t)(sc * 64 + r) * 1024 + c * 8;
            const uint32_t so = SWZ128(r * 128 + c * 16);
            cpa16(kb + so, k + go);
            cpa16(kb + KVT + so, v + go);
        }
        asm volatile("cp.async.commit_group;" ::: "memory");
    };

    float acc[8][4];
    #pragma unroll
    for (int i = 0; i < 8; ++i)
        #pragma unroll
        for (int r = 0; r < 4; ++r) acc[i][r] = 0.f;
    float ks_acc = 0.f;

    const int se = tid & 63;
    const int srg = tid >> 6;
    const int trow  = ((lid >> 4) << 3) + (lid & 7);
    const int tcolh = ((lid >> 3) & 1) << 3;

    load_sc(0, 0);
    for (int sc = 0; sc < 8; ++sc) {
        const int buf = sc & 1;
        if (sc < 7) {
            load_sc(sc + 1, buf ^ 1);
            asm volatile("cp.async.wait_group 1;" ::: "memory");
        } else {
            asm volatile("cp.async.wait_group 0;" ::: "memory");
        }
        __syncthreads();
        const uint32_t kb = sb + buf * 2 * KVT;
        #pragma unroll
        for (int ks = 0; ks < 4; ++ks) {
            uint32_t af[4], bf[4][4];
            ldmx4t(af, kb + SWZ128((ks * 16 + trow) * 128 +
                                   (wid * 16 + tcolh) * 2));
            #pragma unroll
            for (int nj = 0; nj < 4; ++nj)
                ldmx4t(bf[nj], kb + KVT + SWZ128((ks * 16 + trow) * 128 +
                                                 (nj * 16 + tcolh) * 2));
            #pragma unroll
            for (int ni = 0; ni < 8; ++ni) {
                const int nj = ni >> 1, s = ni & 1;
                mma16816(acc[ni], af, bf[nj][s], bf[nj][s + 2]);
            }
        }
        #pragma unroll 8
        for (int rr = 0; rr < 32; ++rr) {
            const int row = srg * 32 + rr;
            const __half kv16 = *(const __half*)
                ((char*)kvs_raw + buf * 2 * KVT + SWZ128(row * 128 + se * 2));
            ks_acc += __half2float(kv16);
        }
        __syncthreads();
    }
    sks[srg][se] = ks_acc;

    const int qrow = lid >> 2;
    const int qcol = (lid & 3) * 2;
    float* kvo = kvp + (((size_t)(nc * 4 + b)) * 16 + h) * 4096;
    #pragma unroll
    for (int ni = 0; ni < 8; ++ni)
        #pragma unroll
        for (int half = 0; half < 2; ++half) {
            const int dm = wid * 16 + qrow + half * 8;
            *(float2*)(kvo + dm * 64 + ni * 8 + qcol) =
                make_float2(acc[ni][half * 2 + 0], acc[ni][half * 2 + 1]);
        }
    __syncthreads();
    if (tid < 64)
        kmp[(size_t)(nc * 4 + b) * 1024 + h * 64 + tid] =
            sks[0][tid] + sks[1][tid];

    __threadfence();
    if (tid == 0)
        is_last = (atomicAdd(&g_cnt[bh], 1) == 7);
    __syncthreads();
    if (!is_last) return;
    __threadfence();

    for (int i = tid; i < 4096; i += 128) {
        float s = 0.f;
        #pragma unroll
        for (int c = 0; c < 8; ++c)
            s += kvp[(((size_t)(c * 4 + b)) * 16 + h) * 4096 + i];
        const int d = i >> 6, e = i & 63;
        kvt[(size_t)bh * 4096 + e * 64 + d] = __float2half_rn(s * (1.0f / 4096.0f));
    }
    if (tid < 64) {
        float s = 0.f;
        #pragma unroll
        for (int c = 0; c < 8; ++c)
            s += kmp[(size_t)(c * 4 + b) * 1024 + h * 64 + tid];
        km[b * 1024 + h * 64 + tid] = s * (1.0f / 4096.0f);
    }
    if (tid == 0) atomicExch(&g_cnt[bh], 0);
}

// ---------------------------------------------------------------------------
extern "C" void kernel_launch(void* const* d_in, const int* in_sizes, int n_in,
                              void* d_out, int out_size)
{
    const float* x     = (const float*)d_in[0];
    const float* Wq    = (const float*)d_in[1];
    const float* Wkv   = (const float*)d_in[2];
    const float* Wproj = (const float*)d_in[3];
    const float* bproj = (const float*)d_in[4];
    const float* dwc_w = (const float*)d_in[5];
    const float* dwc_b = (const float*)d_in[6];
    float* out = (float*)d_out;

    float *km, *kvp, *kmp;
    __half *q16, *k16, *v16, *c16, *a16, *w16, *kvt16;
    cudaGetSymbolAddress((void**)&q16,   g_q16);
    cudaGetSymbolAddress((void**)&k16,   g_k16);
    cudaGetSymbolAddress((void**)&v16,   g_v16);
    cudaGetSymbolAddress((void**)&c16,   g_c16);
    cudaGetSymbolAddress((void**)&km,    g_kmean);
    cudaGetSymbolAddress((void**)&kvt16, g_kvt16);
    cudaGetSymbolAddress((void**)&kvp,   g_kvp);
    cudaGetSymbolAddress((void**)&kmp,   g_kmp);
    cudaGetSymbolAddress((void**)&a16,   g_a16);
    cudaGetSymbolAddress((void**)&w16,   g_w16);

    cudaFuncSetAttribute(mma_gemm, cudaFuncAttributeMaxDynamicSharedMemorySize,
                         NSTAGE * STG);
    cudaFuncSetAttribute(mma_gemm_qatt,
                         cudaFuncAttributeMaxDynamicSharedMemorySize,
                         NSTAGE * STG);

    const size_t smem = NSTAGE * STG;

    cudaLaunchAttribute pdl[1];
    pdl[0].id = cudaLaunchAttributeProgrammaticStreamSerialization;
    pdl[0].val.programmaticStreamSerializationAllowed = 1;

    // 1: fused conversions (plain launch)
    prep_kernel<<<20480, 256>>>((const float4*)x, (__half2*)a16,
                                Wq, Wkv, Wproj, w16);

    // 2: k/v GEMM (PDL dependent of prep)
    {
        cudaLaunchConfig_t cfg = {};
        cfg.gridDim = dim3(16, 128); cfg.blockDim = dim3(256);
        cfg.dynamicSmemBytes = smem; cfg.stream = 0;
        cfg.attrs = pdl; cfg.numAttrs = 1;
        cudaLaunchKernelEx(&cfg, mma_gemm, a16,
                           (const __half*)(w16 + 1048576),
                           (void*)k16, (void*)v16,
                           (const float*)nullptr, 0);
    }
    // 3: conv -> c16 (PDL dependent of gemm_kv)
    {
        cudaLaunchConfig_t cfg = {};
        cfg.gridDim = dim3(16, 8, 64); cfg.blockDim = dim3(256);
        cfg.dynamicSmemBytes = 0; cfg.stream = 0;
        cfg.attrs = pdl; cfg.numAttrs = 1;
        cudaLaunchKernelEx(&cfg, conv_kernel, (const __half*)v16,
                           dwc_w, dwc_b, c16);
    }
    // 4: kv matrices + kmean + fused reduction (PDL dependent of conv)
    {
        cudaLaunchConfig_t cfg = {};
        cfg.gridDim = dim3(8, 16, 4); cfg.blockDim = dim3(128);
        cfg.dynamicSmemBytes = 0; cfg.stream = 0;
        cfg.attrs = pdl; cfg.numAttrs = 1;
        cudaLaunchKernelEx(&cfg, kvmat_mma, (const __half*)k16,
                           (const __half*)v16, kvp, kmp, kvt16, km);
    }
    // 5: fused q GEMM + z + att (+c16 add) -> q16 (PDL dependent of kvmat;
    //    mainloop overlaps kvmat, wait is inside before kvt/km/c16 use)
    {
        cudaLaunchConfig_t cfg = {};
        cfg.gridDim = dim3(8, 128); cfg.blockDim = dim3(256);
        cfg.dynamicSmemBytes = smem; cfg.stream = 0;
        cfg.attrs = pdl; cfg.numAttrs = 1;
        cudaLaunchKernelEx(&cfg, mma_gemm_qatt, (const __half*)a16,
                           (const __half*)w16, (const __half*)kvt16,
                           (const float*)km, (const __half*)c16, q16);
    }
    // 6: out = (att+conv) @ Wproj + bproj (plain launch; avoids parking
    //    its 96KB-smem blocks inside qatt's residency)
    mma_gemm<<<dim3(8, 128), 256, smem>>>(q16, w16 + 3145728, out, nullptr,
                                          bproj, 1);
}